// round 3
// baseline (speedup 1.0000x reference)
#include <cuda_runtime.h>
#include <mma.h>
#include <math.h>

using namespace nvcuda;

#define B_   2
#define S_   2048
#define D_   1024
#define H_   16
#define DC_  64
#define HC_  16
#define MFF_ 4096
#define DH_  64
#define BS_  (B_*S_)      // 4096
#define BH_  (B_*H_)      // 32

// ---------------- scratch (static device globals; no allocation) ----------------
__device__ float g_hn  [BS_*D_];
__device__ float g_val [BS_*D_];
__device__ float g_zh  [BS_*H_*HC_];
__device__ float g_P   [134217728];   // B*H*S*S raw logits
__device__ float g_rowm[BH_*S_];
__device__ float g_rowl[BH_*S_];
__device__ float g_attn[BS_*D_];
__device__ float g_h1  [BS_*D_];
__device__ float g_hn2 [BS_*D_];
__device__ float g_mid [BS_*MFF_];
__device__ float g_ztmp[BS_*DC_];

__device__ __forceinline__ float to_tf32(float x) {
    float r; asm("cvt.rna.tf32.f32 %0, %1;" : "=f"(r) : "f"(x)); return r;
}

enum { EPI_BIAS = 0, EPI_RES = 1, EPI_GELU = 2 };

// ---------------- generic tf32 GEMM: C = epi(A[M,K] @ B[K,N] + bias) ----------------
template<int BM, int BN, int EPI>
__global__ void __launch_bounds__(256, 2) gemm_tf32(
    const float* __restrict__ A, const float* __restrict__ Bw,
    const float* __restrict__ bias, const float* __restrict__ Rres,
    float* __restrict__ C, int Mdim, int Ndim, int Kdim)
{
    constexpr int BK = 32;
    constexpr int WN = BN / 64;           // warps along N (1 or 2)
    __shared__ float As[BM][BK + 4];
    __shared__ float Bs[BK][BN + 4];

    const int tid = threadIdx.x;
    const int wid = tid >> 5, lane = tid & 31;
    const int wm = wid / WN, wn = wid % WN;
    const int bm0 = blockIdx.y * BM, bn0 = blockIdx.x * BN;

    wmma::fragment<wmma::accumulator, 16, 16, 8, float> acc[2][4];
#pragma unroll
    for (int i = 0; i < 2; i++)
#pragma unroll
        for (int j = 0; j < 4; j++) wmma::fill_fragment(acc[i][j], 0.0f);

    for (int k0 = 0; k0 < Kdim; k0 += BK) {
#pragma unroll
        for (int i = tid; i < BM * 8; i += 256) {
            int r = i >> 3, c = (i & 7) * 4;
            float4 v = *(const float4*)(A + (size_t)(bm0 + r) * Kdim + k0 + c);
            v.x = to_tf32(v.x); v.y = to_tf32(v.y); v.z = to_tf32(v.z); v.w = to_tf32(v.w);
            *(float4*)&As[r][c] = v;
        }
#pragma unroll
        for (int i = tid; i < BK * (BN / 4); i += 256) {
            int r = i / (BN / 4), c = (i % (BN / 4)) * 4;
            float4 v = *(const float4*)(Bw + (size_t)(k0 + r) * Ndim + bn0 + c);
            v.x = to_tf32(v.x); v.y = to_tf32(v.y); v.z = to_tf32(v.z); v.w = to_tf32(v.w);
            *(float4*)&Bs[r][c] = v;
        }
        __syncthreads();
#pragma unroll
        for (int kk = 0; kk < BK; kk += 8) {
            wmma::fragment<wmma::matrix_a, 16, 16, 8, wmma::precision::tf32, wmma::row_major> af[2];
            wmma::fragment<wmma::matrix_b, 16, 16, 8, wmma::precision::tf32, wmma::row_major> bf[4];
            wmma::load_matrix_sync(af[0], &As[wm * 32][kk], BK + 4);
            wmma::load_matrix_sync(af[1], &As[wm * 32 + 16][kk], BK + 4);
#pragma unroll
            for (int j = 0; j < 4; j++)
                wmma::load_matrix_sync(bf[j], &Bs[kk][wn * 64 + j * 16], BN + 4);
#pragma unroll
            for (int i = 0; i < 2; i++)
#pragma unroll
                for (int j = 0; j < 4; j++)
                    wmma::mma_sync(acc[i][j], af[i], bf[j], acc[i][j]);
        }
        __syncthreads();
    }

    // epilogue via per-warp smem patch (aliases As, safe after final sync)
    float* Cs = &As[0][0] + wid * 256;
#pragma unroll
    for (int i = 0; i < 2; i++) {
#pragma unroll
        for (int j = 0; j < 4; j++) {
            wmma::store_matrix_sync(Cs, acc[i][j], 16, wmma::mem_row_major);
            __syncwarp();
            int r0 = bm0 + wm * 32 + i * 16;
            int c0 = bn0 + wn * 64 + j * 16;
#pragma unroll
            for (int e = lane; e < 256; e += 32) {
                int rr = e >> 4, cc = e & 15;
                float v = Cs[e] + bias[c0 + cc];
                if (EPI == EPI_GELU) v = 0.5f * v * (1.0f + erff(v * 0.70710678118654752f));
                if (EPI == EPI_RES)  v += Rres[(size_t)(r0 + rr) * Ndim + c0 + cc];
                C[(size_t)(r0 + rr) * Ndim + c0 + cc] = v;
            }
            __syncwarp();
        }
    }
}

// ---------------- distance scores + online softmax stats ----------------
// P[bh,q,k] = -softplus(gamma[h]) * max(|zq|^2 + |zk|^2 - 2 zq.zk, 0)  (raw logits)
// rowm/rowl: running max and sum-of-exp per row.
__global__ void __launch_bounds__(256, 2) score_kernel(
    const float* __restrict__ zh, const float* __restrict__ gamma,
    float* __restrict__ P, float* __restrict__ rowm, float* __restrict__ rowl)
{
    __shared__ float zqs[64][17];
    __shared__ float zkt[16][132];   // transposed key tile: [c][k]
    __shared__ float ksq[128];

    const int b = blockIdx.z, h = blockIdx.y;
    const int q0 = blockIdx.x * 64;
    const int tid = threadIdx.x;
    const float gx = gamma[h];
    const float g = (gx > 20.f) ? gx : log1pf(__expf(gx));

    for (int i = tid; i < 64 * 4; i += 256) {
        int r = i >> 2, c = (i & 3) * 4;
        float4 v = *(const float4*)(zh + ((size_t)(b * S_ + q0 + r)) * (H_ * HC_) + h * HC_ + c);
        zqs[r][c] = v.x; zqs[r][c + 1] = v.y; zqs[r][c + 2] = v.z; zqs[r][c + 3] = v.w;
    }
    __syncthreads();

    const int qg = tid >> 4;      // 0..15 -> 4 queries each
    const int kslot = tid & 15;   // 0..15
    float zq[4][16], qsq[4], m[4], l[4];
#pragma unroll
    for (int qi = 0; qi < 4; qi++) {
        float s = 0.f;
#pragma unroll
        for (int c = 0; c < 16; c++) { float v = zqs[qg * 4 + qi][c]; zq[qi][c] = v; s = fmaf(v, v, s); }
        qsq[qi] = s; m[qi] = -INFINITY; l[qi] = 0.f;
    }

    const int bh = b * H_ + h;
    const size_t prow0 = ((size_t)bh * S_ + (q0 + qg * 4)) * S_;

    for (int k0 = 0; k0 < S_; k0 += 128) {
        __syncthreads();
        for (int i = tid; i < 128 * 4; i += 256) {
            int r = i >> 2, c = (i & 3) * 4;
            float4 v = *(const float4*)(zh + ((size_t)(b * S_ + k0 + r)) * (H_ * HC_) + h * HC_ + c);
            zkt[c][r] = v.x; zkt[c + 1][r] = v.y; zkt[c + 2][r] = v.z; zkt[c + 3][r] = v.w;
        }
        __syncthreads();
        if (tid < 128) {
            float s = 0.f;
#pragma unroll
            for (int c = 0; c < 16; c++) { float v = zkt[c][tid]; s = fmaf(v, v, s); }
            ksq[tid] = s;
        }
        __syncthreads();
#pragma unroll
        for (int j = 0; j < 8; j++) {
            int kk = j * 16 + kslot;
            float zk[16];
#pragma unroll
            for (int c = 0; c < 16; c++) zk[c] = zkt[c][kk];
            float kq = ksq[kk];
#pragma unroll
            for (int qi = 0; qi < 4; qi++) {
                float dot = 0.f;
#pragma unroll
                for (int c = 0; c < 16; c++) dot = fmaf(zq[qi][c], zk[c], dot);
                float d = fmaxf(qsq[qi] + kq - 2.f * dot, 0.f);
                float s = -g * d;
                P[prow0 + (size_t)qi * S_ + k0 + kk] = s;
                if (s > m[qi]) { l[qi] = l[qi] * __expf(m[qi] - s) + 1.f; m[qi] = s; }
                else           l[qi] += __expf(s - m[qi]);
            }
        }
    }
    // reduce (m,l) over 16 kslots (contiguous lanes within a half-warp)
#pragma unroll
    for (int off = 8; off > 0; off >>= 1) {
#pragma unroll
        for (int qi = 0; qi < 4; qi++) {
            float m2 = __shfl_xor_sync(0xffffffffu, m[qi], off);
            float l2 = __shfl_xor_sync(0xffffffffu, l[qi], off);
            if (m2 > m[qi]) { l[qi] = l[qi] * __expf(m[qi] - m2) + l2; m[qi] = m2; }
            else            l[qi] += l2 * __expf(m2 - m[qi]);
        }
    }
    if (kslot == 0) {
#pragma unroll
        for (int qi = 0; qi < 4; qi++) {
            rowm[bh * S_ + q0 + qg * 4 + qi] = m[qi];
            rowl[bh * S_ + q0 + qg * 4 + qi] = l[qi];
        }
    }
}

// ---------------- PV: O[b,q,h,:] = softmax(P[bh,q,:]) @ V[b,:,h,:] ----------------
// exp(s - m) applied during A-tile load (each P element read once), 1/l in epilogue.
__global__ void __launch_bounds__(256, 2) pv_gemm(
    const float* __restrict__ P, const float* __restrict__ rowm, const float* __restrict__ rowl,
    const float* __restrict__ V, float* __restrict__ O)
{
    constexpr int BM = 256, BK = 32;
    __shared__ float As[BM][BK + 4];
    __shared__ float Bs[BK][DH_ + 4];
    __shared__ float rm[BM], rl[BM];

    const int tid = threadIdx.x;
    const int wid = tid >> 5, lane = tid & 31;
    const int bh = blockIdx.y;
    const int b = bh >> 4, h = bh & 15;
    const int q0 = blockIdx.x * BM;

    rm[tid] = rowm[bh * S_ + q0 + tid];
    rl[tid] = rowl[bh * S_ + q0 + tid];
    __syncthreads();

    wmma::fragment<wmma::accumulator, 16, 16, 8, float> acc[2][4];
#pragma unroll
    for (int i = 0; i < 2; i++)
#pragma unroll
        for (int j = 0; j < 4; j++) wmma::fill_fragment(acc[i][j], 0.0f);

    const float* Pb = P + (size_t)bh * S_ * S_;
    const float* Vb = V + (size_t)b * S_ * D_ + h * DH_;

    for (int k0 = 0; k0 < S_; k0 += BK) {
#pragma unroll
        for (int i = tid; i < BM * 8; i += 256) {
            int r = i >> 3, c = (i & 7) * 4;
            float4 v = *(const float4*)(Pb + (size_t)(q0 + r) * S_ + k0 + c);
            float mm = rm[r];
            v.x = to_tf32(__expf(v.x - mm)); v.y = to_tf32(__expf(v.y - mm));
            v.z = to_tf32(__expf(v.z - mm)); v.w = to_tf32(__expf(v.w - mm));
            *(float4*)&As[r][c] = v;
        }
#pragma unroll
        for (int i = tid; i < BK * (DH_ / 4); i += 256) {
            int r = i >> 4, c = (i & 15) * 4;
            float4 v = *(const float4*)(Vb + (size_t)(k0 + r) * D_ + c);
            v.x = to_tf32(v.x); v.y = to_tf32(v.y); v.z = to_tf32(v.z); v.w = to_tf32(v.w);
            *(float4*)&Bs[r][c] = v;
        }
        __syncthreads();
#pragma unroll
        for (int kk = 0; kk < BK; kk += 8) {
            wmma::fragment<wmma::matrix_a, 16, 16, 8, wmma::precision::tf32, wmma::row_major> af[2];
            wmma::fragment<wmma::matrix_b, 16, 16, 8, wmma::precision::tf32, wmma::row_major> bf[4];
            wmma::load_matrix_sync(af[0], &As[wid * 32][kk], BK + 4);
            wmma::load_matrix_sync(af[1], &As[wid * 32 + 16][kk], BK + 4);
#pragma unroll
            for (int j = 0; j < 4; j++)
                wmma::load_matrix_sync(bf[j], &Bs[kk][j * 16], DH_ + 4);
#pragma unroll
            for (int i = 0; i < 2; i++)
#pragma unroll
                for (int j = 0; j < 4; j++)
                    wmma::mma_sync(acc[i][j], af[i], bf[j], acc[i][j]);
        }
        __syncthreads();
    }

    float* Cs = &As[0][0] + wid * 256;
#pragma unroll
    for (int i = 0; i < 2; i++) {
#pragma unroll
        for (int j = 0; j < 4; j++) {
            wmma::store_matrix_sync(Cs, acc[i][j], 16, wmma::mem_row_major);
            __syncwarp();
            int r0 = wid * 32 + i * 16;
            int c0 = j * 16;
#pragma unroll
            for (int e = lane; e < 256; e += 32) {
                int rr = e >> 4, cc = e & 15;
                float v = Cs[e] * (1.0f / rl[r0 + rr]);
                O[(size_t)b * S_ * D_ + (size_t)(q0 + r0 + rr) * D_ + h * DH_ + c0 + cc] = v;
            }
            __syncwarp();
        }
    }
}

// ---------------- LayerNorm over last dim ----------------
__global__ void ln_kernel(const float* __restrict__ x, const float* __restrict__ gm,
                          const float* __restrict__ bt, float* __restrict__ y, int Dd)
{
    const int row = blockIdx.x;
    const float* xr = x + (size_t)row * Dd;
    float s = 0.f, s2 = 0.f;
    for (int i = threadIdx.x; i < Dd; i += blockDim.x) {
        float v = xr[i]; s += v; s2 = fmaf(v, v, s2);
    }
    __shared__ float red[2][32];
    const int lane = threadIdx.x & 31, wid = threadIdx.x >> 5;
#pragma unroll
    for (int off = 16; off; off >>= 1) {
        s  += __shfl_xor_sync(0xffffffffu, s, off);
        s2 += __shfl_xor_sync(0xffffffffu, s2, off);
    }
    if (lane == 0) { red[0][wid] = s; red[1][wid] = s2; }
    __syncthreads();
    const int nw = blockDim.x >> 5;
    if (wid == 0) {
        s  = (lane < nw) ? red[0][lane] : 0.f;
        s2 = (lane < nw) ? red[1][lane] : 0.f;
#pragma unroll
        for (int off = 16; off; off >>= 1) {
            s  += __shfl_xor_sync(0xffffffffu, s, off);
            s2 += __shfl_xor_sync(0xffffffffu, s2, off);
        }
        if (lane == 0) { red[0][0] = s; red[1][0] = s2; }
    }
    __syncthreads();
    s = red[0][0]; s2 = red[1][0];
    const float mean = s / Dd;
    const float var  = s2 / Dd - mean * mean;
    const float inv  = rsqrtf(var + 1e-5f);
    float* yr = y + (size_t)row * Dd;
    for (int i = threadIdx.x; i < Dd; i += blockDim.x)
        yr[i] = (xr[i] - mean) * inv * gm[i] + bt[i];
}

// ---------------- launch ----------------
extern "C" void kernel_launch(void* const* d_in, const int* in_sizes, int n_in,
                              void* d_out, int out_size)
{
    const float* h    = (const float*)d_in[0];
    const float* z    = (const float*)d_in[1];
    const float* wv   = (const float*)d_in[2];
    const float* bv   = (const float*)d_in[3];
    const float* wca  = (const float*)d_in[4];
    const float* bca  = (const float*)d_in[5];
    const float* wcn  = (const float*)d_in[6];
    const float* bcn  = (const float*)d_in[7];
    const float* wo   = (const float*)d_in[8];
    const float* bo   = (const float*)d_in[9];
    const float* gamma= (const float*)d_in[10];
    const float* w1   = (const float*)d_in[11];
    const float* b1   = (const float*)d_in[12];
    const float* w2   = (const float*)d_in[13];
    const float* b2   = (const float*)d_in[14];
    const float* ln1g = (const float*)d_in[15];
    const float* ln1b = (const float*)d_in[16];
    const float* ln2g = (const float*)d_in[17];
    const float* ln2b = (const float*)d_in[18];
    const float* lncg = (const float*)d_in[19];
    const float* lncb = (const float*)d_in[20];

    float* out_h = (float*)d_out;
    float* out_z = out_h + (size_t)BS_ * D_;

    float *p_hn, *p_val, *p_zh, *p_P, *p_rm, *p_rl, *p_attn, *p_h1, *p_hn2, *p_mid, *p_ztmp;
    cudaGetSymbolAddress((void**)&p_hn,  g_hn);
    cudaGetSymbolAddress((void**)&p_val, g_val);
    cudaGetSymbolAddress((void**)&p_zh,  g_zh);
    cudaGetSymbolAddress((void**)&p_P,   g_P);
    cudaGetSymbolAddress((void**)&p_rm,  g_rowm);
    cudaGetSymbolAddress((void**)&p_rl,  g_rowl);
    cudaGetSymbolAddress((void**)&p_attn,g_attn);
    cudaGetSymbolAddress((void**)&p_h1,  g_h1);
    cudaGetSymbolAddress((void**)&p_hn2, g_hn2);
    cudaGetSymbolAddress((void**)&p_mid, g_mid);
    cudaGetSymbolAddress((void**)&p_ztmp,g_ztmp);

    // 1) hn = LN1(h)
    ln_kernel<<<BS_, 256>>>(h, ln1g, ln1b, p_hn, D_);
    // 2) value = hn @ wv + bv
    gemm_tf32<128,128,EPI_BIAS><<<dim3(D_/128, BS_/128), 256>>>(p_hn, wv, bv, nullptr, p_val, BS_, D_, D_);
    // 3) zh = z @ wca + bca
    gemm_tf32<128,128,EPI_BIAS><<<dim3(256/128, BS_/128), 256>>>(z, wca, bca, nullptr, p_zh, BS_, 256, DC_);
    // 4) z_tmp = z + (hn @ wcn + bcn)
    gemm_tf32<256,64,EPI_RES><<<dim3(1, BS_/256), 256>>>(p_hn, wcn, bcn, z, p_ztmp, BS_, DC_, D_);
    // 5) scores + softmax stats
    score_kernel<<<dim3(S_/64, H_, B_), 256>>>(p_zh, gamma, p_P, p_rm, p_rl);
    // 6) attn_out = softmax(P) @ V
    pv_gemm<<<dim3(S_/256, BH_), 256>>>(p_P, p_rm, p_rl, p_val, p_attn);
    // 7) h1 = h + (attn_out @ wo + bo)
    gemm_tf32<128,128,EPI_RES><<<dim3(D_/128, BS_/128), 256>>>(p_attn, wo, bo, h, p_h1, BS_, D_, D_);
    // 8) hn2 = LN2(h1)
    ln_kernel<<<BS_, 256>>>(p_h1, ln2g, ln2b, p_hn2, D_);
    // 9) mid = gelu(hn2 @ w1 + b1)
    gemm_tf32<128,128,EPI_GELU><<<dim3(MFF_/128, BS_/128), 256>>>(p_hn2, w1, b1, nullptr, p_mid, BS_, MFF_, D_);
    // 10) out_h = h1 + (mid @ w2 + b2)
    gemm_tf32<128,128,EPI_RES><<<dim3(D_/128, BS_/128), 256>>>(p_mid, w2, b2, p_h1, out_h, BS_, D_, MFF_);
    // 11) out_z = LN_c(z_tmp)
    ln_kernel<<<BS_, 64>>>(p_ztmp, lncg, lncb, out_z, DC_);
}